// round 13
// baseline (speedup 1.0000x reference)
#include <cuda_runtime.h>
#include <cstdint>
#include <cstddef>

// Problem constants
#define D   384
#define S   512
#define NB  8
#define NPOS (NB*S)          // 4096
#define DD  (D*D)            // 147456
#define MC  8                // positions per chunk

// ---------------- scratch (device globals; no allocation allowed) ----------
__device__ int   g_count;
__device__ int   g_list[NPOS];
__device__ float g_toff[D];
__device__ float g_base[D];
__device__ __align__(16) float g_tok[NPOS * D];
__device__ __align__(16) float g_dep[NPOS * D];
__device__ __align__(16) float g_u  [NPOS * D];

// ---------------- packed f32x2 helpers (sm_103a) ----------------------------
__device__ __forceinline__ unsigned long long fma2(unsigned long long a,
                                                   unsigned long long b,
                                                   unsigned long long c) {
    unsigned long long r;
    asm("fma.rn.f32x2 %0, %1, %2, %3;" : "=l"(r) : "l"(a), "l"(b), "l"(c));
    return r;
}
__device__ __forceinline__ unsigned long long pack2(float x, float y) {
    unsigned long long r;
    asm("mov.b64 %0, {%1, %2};" : "=l"(r) : "f"(x), "f"(y));
    return r;
}
__device__ __forceinline__ float hadd2(unsigned long long a) {
    float x, y;
    asm("mov.b64 {%0, %1}, %2;" : "=f"(x), "=f"(y) : "l"(a));
    return x + y;
}

// ---------------- K0: scalars -----------------------------------------------
__global__ void k0_scalars(const float* __restrict__ Wr,
                           const float* __restrict__ bc,
                           const float* __restrict__ br) {
    __shared__ float red[512];
    int t = threadIdx.x;                 // 512 threads
    red[t] = Wr[t];
    __syncthreads();
    for (int ofs = 256; ofs > 0; ofs >>= 1) {
        if (t < ofs) red[t] += red[t + ofs];
        __syncthreads();
    }
    float sumw = red[0];
    if (t < D) {
        float to = tanhf(bc[t]);
        g_toff[t] = to;
        g_base[t] = to * sumw + br[0];
    }
    if (t == 0) g_count = 0;
}

// ---------------- K1: output init + active-position list --------------------
// out[b,s1,:] = base if dep_heads[b,s1]==0 else 0.
// Position (b,s2) is "active" iff dep_heads[b, dep_heads[b,s2]] == 0.
__global__ void k1_init(const int* __restrict__ heads, float* __restrict__ out) {
    int r = blockIdx.x;                  // r = b*S + s1  (also acts as s2 index)
    int t = threadIdx.x;                 // 384 threads
    bool m = (heads[r] == 0);
    out[(size_t)r * D + t] = m ? g_base[t] : 0.0f;
    if (t == 0) {
        int b0 = r & ~(S - 1);           // b*S
        if (heads[b0 + heads[r]] == 0) {
            int idx = atomicAdd(&g_count, 1);
            g_list[idx] = r;
        }
    }
}

// ---------------- K1b: gather tok rows, dep = tanh(tok), zero u -------------
__global__ void k1b_prep(const int* __restrict__ tokens,
                         const float* __restrict__ table) {
    int t = threadIdx.x;                 // 384 threads
    int cnt = g_count;
    for (int i = blockIdx.x; i < cnt; i += gridDim.x) {
        int r = g_list[i];
        int tok_id = tokens[r];
        float v = table[(size_t)tok_id * D + t];
        g_tok[i * D + t] = v;
        g_dep[i * D + t] = tanhf(v);
        g_u  [i * D + t] = 0.0f;
    }
}

// ---------------- K2: bilinear for active positions only --------------------
// u[i][o] = sum_{d,e} tok_i[d] * Wc[o,d,e] * dep_i[e]
// Grid: 768 blocks = (o in [0,384)) x (d-half in {0,1}); 384 threads =
// 4 d-partitions (48 d each) x 96 e-quads. MC=8 halves fma-per-byte vs R5;
// double-buffered 4-row load batches keep >=4 LDG.128 in flight per warp.
#define T2 384

__global__ void __launch_bounds__(T2) k2_bilinear(const float* __restrict__ Wc) {
    __shared__ unsigned long long tok2[MC * 192];
    __shared__ float red[MC * 12];

    const int t  = threadIdx.x;
    const int p  = t / 96;               // d partition 0..3
    const int q  = t - p * 96;           // e quad 0..95
    const int e0 = 4 * q;
    const int o    = blockIdx.x >> 1;
    const int half = blockIdx.x & 1;
    const int dbase = half * 192;        // d in [dbase, dbase+192)
    const int cnt = g_count;

    for (int c0 = 0; c0 < cnt; c0 += MC) {
        // stage tok for this chunk, duplicated for packed FMA: tok2[i*192+dl]=(v,v)
        for (int idx = t; idx < MC * 192; idx += T2) {
            int i  = idx / 192;
            int dl = idx - i * 192;
            float v = 0.0f;
            if (c0 + i < cnt) v = g_tok[(c0 + i) * D + dbase + dl];
            tok2[idx] = pack2(v, v);
        }

        // dep quads in registers (padded positions -> 0 contribute nothing)
        unsigned long long dlo[MC], dhi[MC];
#pragma unroll
        for (int i = 0; i < MC; i++) {
            float4 dv = make_float4(0.f, 0.f, 0.f, 0.f);
            if (c0 + i < cnt)
                dv = *reinterpret_cast<const float4*>(&g_dep[(c0 + i) * D + e0]);
            dlo[i] = pack2(dv.x, dv.y);
            dhi[i] = pack2(dv.z, dv.w);
        }
        __syncthreads();

        unsigned long long s2[MC];
#pragma unroll
        for (int i = 0; i < MC; i++) s2[i] = 0ULL;   // packed (0.0f, 0.0f)

        const float* wrow = Wc + (size_t)o * DD + (size_t)(dbase + p * 48) * D + e0;
        const unsigned long long* tokp = tok2 + p * 48;

        // 48 d-rows in 12 batches of 4, double-buffered in registers
        float4 buf[2][4];
#pragma unroll
        for (int j = 0; j < 4; j++)
            buf[0][j] = *reinterpret_cast<const float4*>(wrow + (size_t)j * D);

#pragma unroll
        for (int blk = 0; blk < 12; blk++) {
            const int cur = blk & 1, nxt = cur ^ 1;
            if (blk < 11) {
#pragma unroll
                for (int j = 0; j < 4; j++)
                    buf[nxt][j] = *reinterpret_cast<const float4*>(
                        wrow + (size_t)((blk + 1) * 4 + j) * D);
            }
#pragma unroll
            for (int j = 0; j < 4; j++) {
                const int dl = blk * 4 + j;
                float4 wv = buf[cur][j];
                unsigned long long wlo = pack2(wv.x, wv.y);
                unsigned long long whi = pack2(wv.z, wv.w);
#pragma unroll
                for (int i = 0; i < MC; i++) {
                    unsigned long long q2 = fma2(wlo, dlo[i], fma2(whi, dhi[i], 0ULL));
                    s2[i] = fma2(tokp[i * 192 + dl], q2, s2[i]);   // += tok[d]*q2
                }
            }
        }
        __syncthreads();

        // reduce over the 384 threads per position
        const int lane = t & 31, wid = t >> 5;   // 12 warps
#pragma unroll
        for (int i = 0; i < MC; i++) {
            float v = hadd2(s2[i]);
            for (int ofs = 16; ofs; ofs >>= 1)
                v += __shfl_down_sync(0xffffffffu, v, ofs);
            if (lane == 0) red[i * 12 + wid] = v;
        }
        __syncthreads();
        if (t < MC && c0 + t < cnt) {
            float acc = 0.0f;
#pragma unroll
            for (int w = 0; w < 12; w++) acc += red[t * 12 + w];
            atomicAdd(&g_u[(c0 + t) * D + o], acc);   // halves commute exactly
        }
        __syncthreads();
    }
}

// ---------------- K3: epilogue + scatter ------------------------------------
__global__ void k3_scatter(const int* __restrict__ heads,
                           const float* __restrict__ Wr,
                           const float* __restrict__ bc,
                           float* __restrict__ out) {
    int t = threadIdx.x;                 // 384 threads
    int cnt = g_count;
    for (int i = blockIdx.x; i < cnt; i += gridDim.x) {
        int r = g_list[i];
        int h = heads[r];
        float w = Wr[r & (S - 1)];
        int row = (r & ~(S - 1)) + h;
        float u = g_u[i * D + t];
        float ton = tanhf(u + bc[t]);
        float c = (ton - g_toff[t]) * w;
        atomicAdd(&out[(size_t)row * D + t], c);
    }
}

// ---------------- launch -----------------------------------------------------
extern "C" void kernel_launch(void* const* d_in, const int* in_sizes, int n_in,
                              void* d_out, int out_size) {
    const int*   tokens = (const int*)  d_in[0];
    // d_in[1] = dep_types: computed-but-discarded in the reference; unused.
    const int*   heads  = (const int*)  d_in[2];
    const float* table  = (const float*)d_in[3];
    const float* Wc     = (const float*)d_in[4];
    const float* bc     = (const float*)d_in[5];
    const float* Wr     = (const float*)d_in[6];
    const float* br     = (const float*)d_in[7];
    float* out = (float*)d_out;

    k0_scalars<<<1, 512>>>(Wr, bc, br);
    k1_init   <<<NPOS, D>>>(heads, out);
    k1b_prep  <<<32, D>>>(tokens, table);
    k2_bilinear<<<2 * D, T2>>>(Wc);
    k3_scatter<<<64, D>>>(heads, Wr, bc, out);
}

// round 14
// speedup vs baseline: 1.4375x; 1.4375x over previous
#include <cuda_runtime.h>
#include <cstdint>
#include <cstddef>

// Problem constants
#define D   384
#define S   512
#define NB  8
#define NPOS (NB*S)          // 4096
#define DD  (D*D)            // 147456
#define MC  8                // positions per chunk (cnt<=8 typical; loop if more)

// ---------------- scratch (device globals; no allocation allowed) ----------
__device__ int   g_count;
__device__ int   g_list[NPOS];
__device__ float g_toff[D];
__device__ float g_base[D];
__device__ __align__(16) float g_tok[NPOS * D];
__device__ __align__(16) float g_dep[NPOS * D];
__device__ __align__(16) float g_u  [NPOS * D];

// ---------------- packed f32x2 helpers (sm_103a) ----------------------------
__device__ __forceinline__ unsigned long long fma2(unsigned long long a,
                                                   unsigned long long b,
                                                   unsigned long long c) {
    unsigned long long r;
    asm("fma.rn.f32x2 %0, %1, %2, %3;" : "=l"(r) : "l"(a), "l"(b), "l"(c));
    return r;
}
__device__ __forceinline__ unsigned long long pack2(float x, float y) {
    unsigned long long r;
    asm("mov.b64 %0, {%1, %2};" : "=l"(r) : "f"(x), "f"(y));
    return r;
}
__device__ __forceinline__ float hadd2(unsigned long long a) {
    float x, y;
    asm("mov.b64 {%0, %1}, %2;" : "=f"(x), "=f"(y) : "l"(a));
    return x + y;
}

// ---------------- K0: scalars -----------------------------------------------
__global__ void k0_scalars(const float* __restrict__ Wr,
                           const float* __restrict__ bc,
                           const float* __restrict__ br) {
    __shared__ float red[512];
    int t = threadIdx.x;                 // 512 threads
    red[t] = Wr[t];
    __syncthreads();
    for (int ofs = 256; ofs > 0; ofs >>= 1) {
        if (t < ofs) red[t] += red[t + ofs];
        __syncthreads();
    }
    float sumw = red[0];
    if (t < D) {
        float to = tanhf(bc[t]);
        g_toff[t] = to;
        g_base[t] = to * sumw + br[0];
    }
    if (t == 0) g_count = 0;
}

// ---------------- K1: output init + active-position list --------------------
// out[b,s1,:] = base if dep_heads[b,s1]==0 else 0.
// Position (b,s2) is "active" iff dep_heads[b, dep_heads[b,s2]] == 0.
__global__ void k1_init(const int* __restrict__ heads, float* __restrict__ out) {
    int r = blockIdx.x;                  // r = b*S + s1  (also acts as s2 index)
    int t = threadIdx.x;                 // 384 threads
    bool m = (heads[r] == 0);
    out[(size_t)r * D + t] = m ? g_base[t] : 0.0f;
    if (t == 0) {
        int b0 = r & ~(S - 1);           // b*S
        if (heads[b0 + heads[r]] == 0) {
            int idx = atomicAdd(&g_count, 1);
            g_list[idx] = r;
        }
    }
}

// ---------------- K1b: gather tok rows, dep = tanh(tok), zero u -------------
__global__ void k1b_prep(const int* __restrict__ tokens,
                         const float* __restrict__ table) {
    int t = threadIdx.x;                 // 384 threads
    int cnt = g_count;
    for (int i = blockIdx.x; i < cnt; i += gridDim.x) {
        int r = g_list[i];
        int tok_id = tokens[r];
        float v = table[(size_t)tok_id * D + t];
        g_tok[i * D + t] = v;
        g_dep[i * D + t] = tanhf(v);
        g_u  [i * D + t] = 0.0f;
    }
}

// ---------------- K2: bilinear for active positions only --------------------
// u[i][o] = sum_{d,e} tok_i[d] * Wc[o,d,e] * dep_i[e]
// Grid: 1536 blocks = (o in [0,384)) x (d-quarter in [0,4)); 384 threads =
// 4 d-partitions (24 rows each, fully unrolled, immediate-offset LDG) x
// 96 e-quads. Reg budget targets 80 -> 2 blocks/SM (24 warps).
#define T2 384

__global__ void __launch_bounds__(T2, 2) k2_bilinear(const float* __restrict__ Wc) {
    __shared__ unsigned long long tok2[MC * 96];   // this quarter's tok, packed (v,v)
    __shared__ float red[MC * 12];

    const int t  = threadIdx.x;
    const int p  = t / 96;               // d partition 0..3 (24 rows each)
    const int q  = t - p * 96;           // e quad 0..95
    const int e0 = 4 * q;
    const int o  = blockIdx.x >> 2;
    const int qd = blockIdx.x & 3;
    const int dbase = qd * 96;           // d in [dbase, dbase+96)
    const int cnt = g_count;

    for (int c0 = 0; c0 < cnt; c0 += MC) {
        // stage tok for this quarter, packed: tok2[i*96 + dl] = (v,v), dl in [0,96)
        for (int idx = t; idx < MC * 96; idx += T2) {
            int i  = idx / 96;
            int dl = idx - i * 96;
            float v = 0.0f;
            if (c0 + i < cnt) v = g_tok[(c0 + i) * D + dbase + dl];
            tok2[idx] = pack2(v, v);
        }

        // dep quads in registers (padded positions -> 0 contribute nothing)
        unsigned long long dlo[MC], dhi[MC];
#pragma unroll
        for (int i = 0; i < MC; i++) {
            float4 dv = make_float4(0.f, 0.f, 0.f, 0.f);
            if (c0 + i < cnt)
                dv = *reinterpret_cast<const float4*>(&g_dep[(c0 + i) * D + e0]);
            dlo[i] = pack2(dv.x, dv.y);
            dhi[i] = pack2(dv.z, dv.w);
        }
        __syncthreads();

        unsigned long long s2[MC];
#pragma unroll
        for (int i = 0; i < MC; i++) s2[i] = 0ULL;   // packed (0.0f, 0.0f)

        // one base pointer; 24 rows via compile-time immediate offsets
        const float* wrow = Wc + (size_t)o * DD + (size_t)(dbase + p * 24) * D + e0;
        const unsigned long long* tokp = tok2 + p * 24;

#pragma unroll
        for (int j = 0; j < 24; ++j) {
            float4 wv = *reinterpret_cast<const float4*>(wrow + j * D);
            unsigned long long wlo = pack2(wv.x, wv.y);
            unsigned long long whi = pack2(wv.z, wv.w);
#pragma unroll
            for (int i = 0; i < MC; i++) {
                // q2 = (w0*d0 + w2*d2, w1*d1 + w3*d3); then s2 += tok[d] * q2
                unsigned long long q2 = fma2(wlo, dlo[i], fma2(whi, dhi[i], 0ULL));
                s2[i] = fma2(tokp[i * 96 + j], q2, s2[i]);
            }
        }
        __syncthreads();

        // reduce over the 384 threads per position
        const int lane = t & 31, wid = t >> 5;   // 12 warps
#pragma unroll
        for (int i = 0; i < MC; i++) {
            float v = hadd2(s2[i]);
            for (int ofs = 16; ofs; ofs >>= 1)
                v += __shfl_down_sync(0xffffffffu, v, ofs);
            if (lane == 0) red[i * 12 + wid] = v;
        }
        __syncthreads();
        if (t < MC && c0 + t < cnt) {
            float acc = 0.0f;
#pragma unroll
            for (int w = 0; w < 12; w++) acc += red[t * 12 + w];
            atomicAdd(&g_u[(c0 + t) * D + o], acc);   // quarters commute exactly
        }
        __syncthreads();
    }
}

// ---------------- K3: epilogue + scatter ------------------------------------
__global__ void k3_scatter(const int* __restrict__ heads,
                           const float* __restrict__ Wr,
                           const float* __restrict__ bc,
                           float* __restrict__ out) {
    int t = threadIdx.x;                 // 384 threads
    int cnt = g_count;
    for (int i = blockIdx.x; i < cnt; i += gridDim.x) {
        int r = g_list[i];
        int h = heads[r];
        float w = Wr[r & (S - 1)];
        int row = (r & ~(S - 1)) + h;
        float u = g_u[i * D + t];
        float ton = tanhf(u + bc[t]);
        float c = (ton - g_toff[t]) * w;
        atomicAdd(&out[(size_t)row * D + t], c);
    }
}

// ---------------- launch -----------------------------------------------------
extern "C" void kernel_launch(void* const* d_in, const int* in_sizes, int n_in,
                              void* d_out, int out_size) {
    const int*   tokens = (const int*)  d_in[0];
    // d_in[1] = dep_types: computed-but-discarded in the reference; unused.
    const int*   heads  = (const int*)  d_in[2];
    const float* table  = (const float*)d_in[3];
    const float* Wc     = (const float*)d_in[4];
    const float* bc     = (const float*)d_in[5];
    const float* Wr     = (const float*)d_in[6];
    const float* br     = (const float*)d_in[7];
    float* out = (float*)d_out;

    k0_scalars<<<1, 512>>>(Wr, bc, br);
    k1_init   <<<NPOS, D>>>(heads, out);
    k1b_prep  <<<32, D>>>(tokens, table);
    k2_bilinear<<<4 * D, T2>>>(Wc);      // 1536 blocks: (o, d-quarter)
    k3_scatter<<<64, D>>>(heads, Wr, bc, out);
}

// round 15
// speedup vs baseline: 1.4937x; 1.0391x over previous
#include <cuda_runtime.h>
#include <cstdint>
#include <cstddef>

// Problem constants
#define D   384
#define S   512
#define NB  8
#define NPOS (NB*S)          // 4096
#define DD  (D*D)            // 147456
#define MC  8                // positions per chunk (cnt<=8 typical; loop if more)
#define NTILES (4*D)         // 1536 = 384 o-channels x 4 d-quarters

// ---------------- scratch (device globals; no allocation allowed) ----------
__device__ int   g_count;
__device__ int   g_tick;
__device__ int   g_list[NPOS];
__device__ float g_toff[D];
__device__ float g_base[D];
__device__ __align__(16) float g_tok[NPOS * D];
__device__ __align__(16) float g_dep[NPOS * D];
__device__ __align__(16) float g_u  [NPOS * D];

// ---------------- packed f32x2 helpers (sm_103a) ----------------------------
__device__ __forceinline__ unsigned long long fma2(unsigned long long a,
                                                   unsigned long long b,
                                                   unsigned long long c) {
    unsigned long long r;
    asm("fma.rn.f32x2 %0, %1, %2, %3;" : "=l"(r) : "l"(a), "l"(b), "l"(c));
    return r;
}
__device__ __forceinline__ unsigned long long pack2(float x, float y) {
    unsigned long long r;
    asm("mov.b64 %0, {%1, %2};" : "=l"(r) : "f"(x), "f"(y));
    return r;
}
__device__ __forceinline__ float hadd2(unsigned long long a) {
    float x, y;
    asm("mov.b64 {%0, %1}, %2;" : "=f"(x), "=f"(y) : "l"(a));
    return x + y;
}

// ---------------- K0: scalars + counter resets ------------------------------
__global__ void k0_scalars(const float* __restrict__ Wr,
                           const float* __restrict__ bc,
                           const float* __restrict__ br) {
    __shared__ float red[512];
    int t = threadIdx.x;                 // 512 threads
    red[t] = Wr[t];
    __syncthreads();
    for (int ofs = 256; ofs > 0; ofs >>= 1) {
        if (t < ofs) red[t] += red[t + ofs];
        __syncthreads();
    }
    float sumw = red[0];
    if (t < D) {
        float to = tanhf(bc[t]);
        g_toff[t] = to;
        g_base[t] = to * sumw + br[0];
    }
    if (t == 0) { g_count = 0; g_tick = 0; }
}

// ---------------- K1: output init + active-position list --------------------
__global__ void k1_init(const int* __restrict__ heads, float* __restrict__ out) {
    int r = blockIdx.x;                  // r = b*S + s1  (also acts as s2 index)
    int t = threadIdx.x;                 // 384 threads
    bool m = (heads[r] == 0);
    out[(size_t)r * D + t] = m ? g_base[t] : 0.0f;
    if (t == 0) {
        int b0 = r & ~(S - 1);           // b*S
        if (heads[b0 + heads[r]] == 0) {
            int idx = atomicAdd(&g_count, 1);
            g_list[idx] = r;
        }
    }
}

// ---------------- K1b: gather tok rows, dep = tanh(tok), zero u -------------
__global__ void k1b_prep(const int* __restrict__ tokens,
                         const float* __restrict__ table) {
    int t = threadIdx.x;                 // 384 threads
    int cnt = g_count;
    for (int i = blockIdx.x; i < cnt; i += gridDim.x) {
        int r = g_list[i];
        int tok_id = tokens[r];
        float v = table[(size_t)tok_id * D + t];
        g_tok[i * D + t] = v;
        g_dep[i * D + t] = tanhf(v);
        g_u  [i * D + t] = 0.0f;
    }
}

// ---------------- K2: bilinear for active positions only --------------------
// u[i][o] = sum_{d,e} tok_i[d] * Wc[o,d,e] * dep_i[e]
// Persistent: 296 blocks (2/SM), ticket over 1536 tiles = (o, d-quarter).
// 384 threads = 4 d-partitions (24 rows, unrolled, imm-offset LDG) x 96 e-quads.
// tok staged i-major so LDS.128 fetches two positions per instruction.
#define T2 384

__global__ void __launch_bounds__(T2, 2) k2_bilinear(const float* __restrict__ Wc) {
    __shared__ __align__(16) unsigned long long tok2[96 * MC]; // [dl][i], (v,v) pairs
    __shared__ float red[MC * 12];
    __shared__ int s_tile;

    const int t  = threadIdx.x;
    const int p  = t / 96;               // d partition 0..3 (24 rows each)
    const int q  = t - p * 96;           // e quad 0..95
    const int e0 = 4 * q;
    const int cnt = g_count;

    for (;;) {
        __syncthreads();                 // protect s_tile / tok2 reuse
        if (t == 0) s_tile = atomicAdd(&g_tick, 1);
        __syncthreads();
        const int tile = s_tile;
        if (tile >= NTILES) break;
        const int o  = tile >> 2;
        const int qd = tile & 3;
        const int dbase = qd * 96;       // d in [dbase, dbase+96)

        for (int c0 = 0; c0 < cnt; c0 += MC) {
            // stage tok i-major: tok2[dl*MC + i] = (v,v)
            for (int idx = t; idx < MC * 96; idx += T2) {
                int dl = idx / MC;
                int i  = idx - dl * MC;
                float v = 0.0f;
                if (c0 + i < cnt) v = g_tok[(c0 + i) * D + dbase + dl];
                tok2[idx] = pack2(v, v);
            }

            // dep quads in registers (padded positions -> 0 contribute nothing)
            unsigned long long dlo[MC], dhi[MC];
#pragma unroll
            for (int i = 0; i < MC; i++) {
                float4 dv = make_float4(0.f, 0.f, 0.f, 0.f);
                if (c0 + i < cnt)
                    dv = *reinterpret_cast<const float4*>(&g_dep[(c0 + i) * D + e0]);
                dlo[i] = pack2(dv.x, dv.y);
                dhi[i] = pack2(dv.z, dv.w);
            }
            __syncthreads();

            unsigned long long s2[MC];
#pragma unroll
            for (int i = 0; i < MC; i++) s2[i] = 0ULL;   // packed (0,0)

            const float* wrow = Wc + (size_t)o * DD
                                   + (size_t)(dbase + p * 24) * D + e0;
            const ulonglong2* tokp =
                reinterpret_cast<const ulonglong2*>(tok2 + p * 24 * MC);

#pragma unroll
            for (int j = 0; j < 24; ++j) {
                float4 wv = *reinterpret_cast<const float4*>(wrow + j * D);
                unsigned long long wlo = pack2(wv.x, wv.y);
                unsigned long long whi = pack2(wv.z, wv.w);
#pragma unroll
                for (int ii = 0; ii < MC / 2; ii++) {
                    // one LDS.128: tok pairs for positions 2ii and 2ii+1
                    ulonglong2 tk = tokp[j * (MC / 2) + ii];
                    unsigned long long qa =
                        fma2(wlo, dlo[2 * ii],     fma2(whi, dhi[2 * ii],     0ULL));
                    unsigned long long qb =
                        fma2(wlo, dlo[2 * ii + 1], fma2(whi, dhi[2 * ii + 1], 0ULL));
                    s2[2 * ii]     = fma2(tk.x, qa, s2[2 * ii]);
                    s2[2 * ii + 1] = fma2(tk.y, qb, s2[2 * ii + 1]);
                }
            }
            __syncthreads();

            // reduce over the 384 threads per position
            const int lane = t & 31, wid = t >> 5;   // 12 warps
#pragma unroll
            for (int i = 0; i < MC; i++) {
                float v = hadd2(s2[i]);
                for (int ofs = 16; ofs; ofs >>= 1)
                    v += __shfl_down_sync(0xffffffffu, v, ofs);
                if (lane == 0) red[i * 12 + wid] = v;
            }
            __syncthreads();
            if (t < MC && c0 + t < cnt) {
                float acc = 0.0f;
#pragma unroll
                for (int w = 0; w < 12; w++) acc += red[t * 12 + w];
                atomicAdd(&g_u[(c0 + t) * D + o], acc);   // quarters commute
            }
        }
    }
}

// ---------------- K3: epilogue + scatter ------------------------------------
__global__ void k3_scatter(const int* __restrict__ heads,
                           const float* __restrict__ Wr,
                           const float* __restrict__ bc,
                           float* __restrict__ out) {
    int t = threadIdx.x;                 // 384 threads
    int cnt = g_count;
    for (int i = blockIdx.x; i < cnt; i += gridDim.x) {
        int r = g_list[i];
        int h = heads[r];
        float w = Wr[r & (S - 1)];
        int row = (r & ~(S - 1)) + h;
        float u = g_u[i * D + t];
        float ton = tanhf(u + bc[t]);
        float c = (ton - g_toff[t]) * w;
        atomicAdd(&out[(size_t)row * D + t], c);
    }
}

// ---------------- launch -----------------------------------------------------
extern "C" void kernel_launch(void* const* d_in, const int* in_sizes, int n_in,
                              void* d_out, int out_size) {
    const int*   tokens = (const int*)  d_in[0];
    // d_in[1] = dep_types: computed-but-discarded in the reference; unused.
    const int*   heads  = (const int*)  d_in[2];
    const float* table  = (const float*)d_in[3];
    const float* Wc     = (const float*)d_in[4];
    const float* bc     = (const float*)d_in[5];
    const float* Wr     = (const float*)d_in[6];
    const float* br     = (const float*)d_in[7];
    float* out = (float*)d_out;

    k0_scalars<<<1, 512>>>(Wr, bc, br);
    k1_init   <<<NPOS, D>>>(heads, out);
    k1b_prep  <<<32, D>>>(tokens, table);
    k2_bilinear<<<296, T2>>>(Wc);        // persistent: 2/SM x 148 SMs
    k3_scatter<<<64, D>>>(heads, Wr, bc, out);
}